// round 15
// baseline (speedup 1.0000x reference)
#include <cuda_runtime.h>
#include <cuda_bf16.h>
#include <cuda_fp16.h>

typedef unsigned int u32;
typedef unsigned long long u64;

#define Bz 8
#define Cz 2048
#define HD 128
#define QT 128
#define KT 64
#define NIT (Cz/KT)
#define LOG2E 1.4426950408889634f

// hi/lo scratch, packed as 2-elem words (even col in low half)
__device__ u32 g_Qhi[Bz*Cz*64], g_Qlo[Bz*Cz*64];        // bf16x2 [b*C + c][64]
__device__ u32 g_Khi[Bz*4*Cz*16], g_Klo[Bz*4*Cz*16];    // bf16x2 [b*4+h][key][16]
__device__ u32 g_Vhi[Bz*4*Cz*16], g_Vlo[Bz*4*Cz*16];    // fp16x2 [b*4+h][key][16]
__device__ u32 g_Ahi[Bz*Cz*64], g_Alo[Bz*Cz*64];        // bf16x2 attention output

// ---------------- helpers ---------------------------------------------------
__device__ __forceinline__ u32 smem_u32(const void* p) {
    u32 a;
    asm("{ .reg .u64 t; cvta.to.shared.u64 t, %1; cvt.u32.u64 %0, t; }" : "=r"(a) : "l"(p));
    return a;
}
__device__ __forceinline__ u32 cvt2(float hi, float lo) {       // bf16x2
    u32 r; asm("cvt.rn.bf16x2.f32 %0, %1, %2;" : "=r"(r) : "f"(hi), "f"(lo)); return r;
}
__device__ __forceinline__ u32 cvt2h(float hi, float lo) {      // fp16x2
    u32 r; asm("cvt.rn.f16x2.f32 %0, %1, %2;" : "=r"(r) : "f"(hi), "f"(lo)); return r;
}
__device__ __forceinline__ float2 ub2(u32 v) {
    __nv_bfloat162 t = *reinterpret_cast<__nv_bfloat162*>(&v);
    return __bfloat1622float2(t);
}
__device__ __forceinline__ float2 uh2(u32 v) {
    __half2 t = *reinterpret_cast<__half2*>(&v);
    return __half22float2(t);
}
__device__ __forceinline__ void split2(float x0, float x1, u32& hi, u32& lo) {
    hi = cvt2(x1, x0);
    float2 f = ub2(hi);
    lo = cvt2(x1 - f.y, x0 - f.x);
}
__device__ __forceinline__ void split2h(float x0, float x1, u32& hi, u32& lo) {
    hi = cvt2h(x1, x0);
    float2 f = uh2(hi);
    lo = cvt2h(x1 - f.y, x0 - f.x);
}
__device__ __forceinline__ float ex2f(float x) {
    float y; asm("ex2.approx.f32 %0, %1;" : "=f"(y) : "f"(x)); return y;
}
__device__ __forceinline__ void ldsm4(u32* r, u32 addr) {
    asm volatile("ldmatrix.sync.aligned.m8n8.x4.shared.b16 {%0,%1,%2,%3}, [%4];"
        : "=r"(r[0]), "=r"(r[1]), "=r"(r[2]), "=r"(r[3]) : "r"(addr));
}
__device__ __forceinline__ void ldsm4t(u32* r, u32 addr) {
    asm volatile("ldmatrix.sync.aligned.m8n8.x4.trans.shared.b16 {%0,%1,%2,%3}, [%4];"
        : "=r"(r[0]), "=r"(r[1]), "=r"(r[2]), "=r"(r[3]) : "r"(addr));
}
__device__ __forceinline__ void mma16816(float* c, const u32* a, const u32* b) {
    asm volatile("mma.sync.aligned.m16n8k16.row.col.f32.bf16.bf16.f32 "
        "{%0,%1,%2,%3}, {%4,%5,%6,%7}, {%8,%9}, {%0,%1,%2,%3};"
        : "+f"(c[0]), "+f"(c[1]), "+f"(c[2]), "+f"(c[3])
        : "r"(a[0]), "r"(a[1]), "r"(a[2]), "r"(a[3]), "r"(b[0]), "r"(b[1]));
}
__device__ __forceinline__ void mma16816h(float* c, const u32* a, const u32* b) {
    asm volatile("mma.sync.aligned.m16n8k16.row.col.f32.f16.f16.f32 "
        "{%0,%1,%2,%3}, {%4,%5,%6,%7}, {%8,%9}, {%0,%1,%2,%3};"
        : "+f"(c[0]), "+f"(c[1]), "+f"(c[2]), "+f"(c[3])
        : "r"(a[0]), "r"(a[1]), "r"(a[2]), "r"(a[3]), "r"(b[0]), "r"(b[1]));
}

// ---------------------------------------------------------------------------
// Kernel 1: QKV projection via mma.sync (bf16 hi/lo x3). grid (B*C/64, 3),
// block 256. Q/K pre-split bf16 hi/lo; V pre-split fp16 hi/lo.
// ---------------------------------------------------------------------------
#define GX_HI 0
#define GX_LO 17408
#define GW_HI 34816
#define GW_LO 69632
#define GSMEM 104448

__global__ __launch_bounds__(256, 2) void qkv_mma(
    const float* __restrict__ x, const float* __restrict__ Wq,
    const float* __restrict__ Wk, const float* __restrict__ Wv)
{
    extern __shared__ char sm[];
    const u32 smb = smem_u32(sm);
    const int rt = blockIdx.x, mqkv = blockIdx.y, tid = threadIdx.x;
    const float* __restrict__ W = (mqkv == 0) ? Wq : ((mqkv == 1) ? Wk : Wv);

    {
        const float4* xg = (const float4*)(x + (size_t)rt * 64 * 128);
        #pragma unroll
        for (int i = 0; i < 8; i++) {
            const int e = tid + i*256, row = e >> 5, c4 = e & 31;
            const float4 v = xg[e];
            u32 h0, h1, l0, l1;
            split2(v.x, v.y, h0, l0); split2(v.z, v.w, h1, l1);
            *(uint2*)(sm + GX_HI + row*272 + c4*8) = make_uint2(h0, h1);
            *(uint2*)(sm + GX_LO + row*272 + c4*8) = make_uint2(l0, l1);
        }
        const float4* wg = (const float4*)W;
        #pragma unroll
        for (int i = 0; i < 16; i++) {
            const int e = tid + i*256, row = e >> 5, c4 = e & 31;
            const float4 v = wg[e];
            u32 h0, h1, l0, l1;
            split2(v.x, v.y, h0, l0); split2(v.z, v.w, h1, l1);
            *(uint2*)(sm + GW_HI + row*272 + c4*8) = make_uint2(h0, h1);
            *(uint2*)(sm + GW_LO + row*272 + c4*8) = make_uint2(l0, l1);
        }
    }
    __syncthreads();

    const int wid = tid >> 5, lane = tid & 31;
    const int mi = wid >> 1, half = wid & 1;
    const int r = lane >> 2, qq = lane & 3;

    float c[8][4];
    #pragma unroll
    for (int i = 0; i < 8; i++)
        #pragma unroll
        for (int k = 0; k < 4; k++) c[i][k] = 0.f;

    const u32 fofs = (lane & 15)*272 + (lane >> 4)*16;
    const u32 aHi = smb + GX_HI + mi*16*272 + fofs;
    const u32 aLo = smb + GX_LO + mi*16*272 + fofs;
    const u32 bHi = smb + GW_HI + half*128 + fofs;
    const u32 bLo = smb + GW_LO + half*128 + fofs;

    #pragma unroll 1
    for (int kk = 0; kk < 8; kk++) {
        u32 ah[4], al[4];
        ldsm4(ah, aHi + kk*32);
        ldsm4(al, aLo + kk*32);
        u32 bh[16], bl[16];
        #pragma unroll
        for (int nt = 0; nt < 4; nt++) {
            ldsm4t(bh + nt*4, bHi + kk*16*272 + nt*32);
            ldsm4t(bl + nt*4, bLo + kk*16*272 + nt*32);
        }
        #pragma unroll
        for (int n8 = 0; n8 < 8; n8++) {
            mma16816(c[n8], ah, bh + n8*2);
            mma16816(c[n8], ah, bl + n8*2);
            mma16816(c[n8], al, bh + n8*2);
        }
    }

    const float scale = (mqkv == 0) ? 0.17677669529663687f : 1.0f;
    const int grow0 = rt*64 + mi*16 + r;
    #pragma unroll
    for (int n8 = 0; n8 < 8; n8++) {
        const int col = half*64 + n8*8 + 2*qq;
        #pragma unroll
        for (int rr = 0; rr < 2; rr++) {
            const int grow = grow0 + rr*8;
            u32 hi, lo;
            if (mqkv == 2) split2h(c[n8][2*rr], c[n8][2*rr+1], hi, lo);
            else           split2(c[n8][2*rr]*scale, c[n8][2*rr+1]*scale, hi, lo);
            if (mqkv == 0) {
                g_Qhi[(size_t)grow*64 + (col >> 1)] = hi;
                g_Qlo[(size_t)grow*64 + (col >> 1)] = lo;
            } else {
                const int bb = grow >> 11, key = grow & 2047;
                const int hh = col >> 5, d2 = (col & 31) >> 1;
                const size_t gi = ((size_t)(bb*4 + hh)*2048 + key)*16 + d2;
                if (mqkv == 1) { g_Khi[gi] = hi; g_Klo[gi] = lo; }
                else           { g_Vhi[gi] = hi; g_Vlo[gi] = lo; }
            }
        }
    }
}

// ---------------------------------------------------------------------------
// Kernel 2: attention. grid (C/128, B), block 512, 16 warps = (h, qsub).
// Each warp: 32 q-rows x 1 head. QK bf16 hi/lo x3; PV fp16 (P single, V hi/lo).
// ---------------------------------------------------------------------------
#define K_HI 0          // [4][64][80B]
#define K_LO 20480
#define V_HI 40960
#define V_LO 61440
#define ADJ  81920      // [128][68] f32 (premultiplied by log2e)
#define ASMEM 116736

__global__ __launch_bounds__(512, 1) void attn_mma(const float* __restrict__ adj)
{
    extern __shared__ char sm[];
    const u32 smb = smem_u32(sm);
    const int tid = threadIdx.x, wid = tid >> 5, lane = tid & 31;
    const int h = wid & 3, qsub = wid >> 2;
    const int r = lane >> 2, qq = lane & 3;
    const int q0 = blockIdx.x * QT, b = blockIdx.y;

    // ---- Q fragments (2 m16 tiles x 2 k16 slices) ----
    u32 qhi[2][2][4], qlo[2][2][4];
    {
        const u32* Qh = g_Qhi + ((size_t)(b*Cz) + q0 + qsub*32)*64 + h*16;
        const u32* Ql = g_Qlo + ((size_t)(b*Cz) + q0 + qsub*32)*64 + h*16;
        #pragma unroll
        for (int m = 0; m < 2; m++)
            #pragma unroll
            for (int j = 0; j < 2; j++)
                #pragma unroll
                for (int p = 0; p < 4; p++) {
                    const int row = 16*m + r + (p & 1)*8;
                    const int ci  = 8*j + qq + (p >> 1)*4;
                    qhi[m][j][p] = Qh[(size_t)row*64 + ci];
                    qlo[m][j][p] = Ql[(size_t)row*64 + ci];
                }
    }

    float o[2][4][4];
    #pragma unroll
    for (int m = 0; m < 2; m++)
        #pragma unroll
        for (int dt = 0; dt < 4; dt++)
            #pragma unroll
            for (int k = 0; k < 4; k++) o[m][dt][k] = 0.f;
    float rs[4] = {0.f, 0.f, 0.f, 0.f};

    const u32 kofs = (lane & 7)*80 + (lane >> 3)*16;
    const u32 vofs = (lane & 15)*80 + (lane >> 4)*16;
    const u32 KhiB = smb + K_HI + h*5120 + kofs;
    const u32 KloB = smb + K_LO + h*5120 + kofs;
    const u32 VhiB = smb + V_HI + h*5120 + vofs;
    const u32 VloB = smb + V_LO + h*5120 + vofs;
    const float* adjs  = (const float*)(sm + ADJ) + (qsub*32 + r)*68 + 2*qq;
    const float* adj_g = adj + ((size_t)b*Cz + q0)*Cz;

    const u32* KhiG = g_Khi + (size_t)b*4*2048*16;
    const u32* KloG = g_Klo + (size_t)b*4*2048*16;
    const u32* VhiG = g_Vhi + (size_t)b*4*2048*16;
    const u32* VloG = g_Vlo + (size_t)b*4*2048*16;

    #pragma unroll 1
    for (int it = 0; it < NIT; it++) {
        const int k0 = it * KT;
        __syncthreads();
        // ---- stage K/V (pure uint4 copies; 1024 uint4 per array) ----
        #pragma unroll
        for (int i = 0; i < 2; i++) {
            const int e = tid + i*512;
            const int hh = e >> 8, key = (e >> 2) & 63, part = e & 3;
            const size_t gi = ((size_t)hh*2048 + k0 + key)*16 + part*4;
            const u32 so = (u32)(hh*5120 + key*80 + part*16);
            *(uint4*)(sm + K_HI + so) = *(const uint4*)(KhiG + gi);
            *(uint4*)(sm + K_LO + so) = *(const uint4*)(KloG + gi);
            *(uint4*)(sm + V_HI + so) = *(const uint4*)(VhiG + gi);
            *(uint4*)(sm + V_LO + so) = *(const uint4*)(VloG + gi);
        }
        // ---- stage adj premultiplied by log2e (2048 float4) ----
        #pragma unroll
        for (int i = 0; i < 4; i++) {
            const int e = tid + i*512, row = e >> 4, c4 = e & 15;
            float4 a = *(const float4*)(adj_g + (size_t)row*Cz + k0 + c4*4);
            a.x *= LOG2E; a.y *= LOG2E; a.z *= LOG2E; a.w *= LOG2E;
            *(float4*)(sm + ADJ + (row*68 + c4*4)*4) = a;
        }
        __syncthreads();

        #pragma unroll
        for (int j = 0; j < 4; j++) {
            u32 bh0[4], bl0[4], bh1[4], bl1[4];
            ldsm4(bh0, KhiB + (2*j)*640);
            ldsm4(bl0, KloB + (2*j)*640);
            ldsm4(bh1, KhiB + (2*j+1)*640);
            ldsm4(bl1, KloB + (2*j+1)*640);
            u32 vh[8], vl[8];
            ldsm4t(vh,     VhiB + j*1280);
            ldsm4t(vh + 4, VhiB + j*1280 + 32);
            ldsm4t(vl,     VloB + j*1280);
            ldsm4t(vl + 4, VloB + j*1280 + 32);

            #pragma unroll
            for (int m = 0; m < 2; m++) {
                u32 pa[4];
                #pragma unroll
                for (int ii = 0; ii < 2; ii++) {
                    const u32* bh = ii ? bh1 : bh0;
                    const u32* bl = ii ? bl1 : bl0;
                    float S[4] = {0.f, 0.f, 0.f, 0.f};
                    mma16816(S, qhi[m][0], bh);
                    mma16816(S, qhi[m][1], bh + 2);
                    mma16816(S, qhi[m][0], bl);
                    mma16816(S, qhi[m][1], bl + 2);
                    mma16816(S, qlo[m][0], bh);
                    mma16816(S, qlo[m][1], bh + 2);

                    const float* ar = adjs + (16*m)*68 + 8*(2*j + ii);
                    const float2 a01 = *(const float2*)ar;
                    const float2 a23 = *(const float2*)(ar + 8*68);
                    float t0 = S[0]*a01.x; t0 = fmaxf(t0, 0.2f*t0);
                    float t1 = S[1]*a01.y; t1 = fmaxf(t1, 0.2f*t1);
                    float t2 = S[2]*a23.x; t2 = fmaxf(t2, 0.2f*t2);
                    float t3 = S[3]*a23.y; t3 = fmaxf(t3, 0.2f*t3);
                    const float p0 = ex2f(t0), p1 = ex2f(t1);
                    const float p2 = ex2f(t2), p3 = ex2f(t3);
                    rs[2*m]   += p0 + p1;
                    rs[2*m+1] += p2 + p3;
                    pa[2*ii]   = cvt2h(p1, p0);
                    pa[2*ii+1] = cvt2h(p3, p2);
                }
                #pragma unroll
                for (int dt = 0; dt < 4; dt++) {
                    mma16816h(o[m][dt], pa, vh + 2*dt);
                    mma16816h(o[m][dt], pa, vl + 2*dt);
                }
            }
        }
    }

    // ---- rowsum reduce across quad, normalize, split hi/lo, store ----
    #pragma unroll
    for (int k = 0; k < 4; k++) {
        rs[k] += __shfl_xor_sync(0xFFFFFFFFu, rs[k], 1);
        rs[k] += __shfl_xor_sync(0xFFFFFFFFu, rs[k], 2);
    }
    #pragma unroll
    for (int m = 0; m < 2; m++) {
        const float inv0 = 1.0f / rs[2*m], inv1 = 1.0f / rs[2*m+1];
        const int row0 = q0 + qsub*32 + 16*m + r;
        #pragma unroll
        for (int dt = 0; dt < 4; dt++) {
            u32 hi, lo;
            split2(o[m][dt][0]*inv0, o[m][dt][1]*inv0, hi, lo);
            size_t gi = ((size_t)(b*Cz) + row0)*64 + h*16 + dt*4 + qq;
            g_Ahi[gi] = hi; g_Alo[gi] = lo;
            split2(o[m][dt][2]*inv1, o[m][dt][3]*inv1, hi, lo);
            gi = ((size_t)(b*Cz) + row0 + 8)*64 + h*16 + dt*4 + qq;
            g_Ahi[gi] = hi; g_Alo[gi] = lo;
        }
    }
}

// ---------------------------------------------------------------------------
// Kernel 3: output projection via mma.sync, A pre-split. grid (B*C/64), 256.
// ---------------------------------------------------------------------------
__global__ __launch_bounds__(256, 2) void out_mma(
    const float* __restrict__ Wo, const float* __restrict__ bo,
    float* __restrict__ out)
{
    extern __shared__ char sm[];
    const u32 smb = smem_u32(sm);
    const int rt = blockIdx.x, tid = threadIdx.x;

    {
        const uint4* ah = (const uint4*)(g_Ahi + (size_t)rt*64*64);
        const uint4* al = (const uint4*)(g_Alo + (size_t)rt*64*64);
        #pragma unroll
        for (int i = 0; i < 4; i++) {
            const int e = tid + i*256, row = e >> 4, c4 = e & 15;
            *(uint4*)(sm + GX_HI + row*272 + c4*16) = ah[e];
            *(uint4*)(sm + GX_LO + row*272 + c4*16) = al[e];
        }
        const float4* wg = (const float4*)Wo;
        #pragma unroll
        for (int i = 0; i < 16; i++) {
            const int e = tid + i*256, row = e >> 5, c4 = e & 31;
            const float4 v = wg[e];
            u32 h0, h1, l0, l1;
            split2(v.x, v.y, h0, l0); split2(v.z, v.w, h1, l1);
            *(uint2*)(sm + GW_HI + row*272 + c4*8) = make_uint2(h0, h1);
            *(uint2*)(sm + GW_LO + row*272 + c4*8) = make_uint2(l0, l1);
        }
    }
    __syncthreads();

    const int wid = tid >> 5, lane = tid & 31;
    const int mi = wid >> 1, half = wid & 1;
    const int r = lane >> 2, qq = lane & 3;

    float c[8][4];
    #pragma unroll
    for (int i = 0; i < 8; i++)
        #pragma unroll
        for (int k = 0; k < 4; k++) c[i][k] = 0.f;

    const u32 fofs = (lane & 15)*272 + (lane >> 4)*16;
    const u32 aHi = smb + GX_HI + mi*16*272 + fofs;
    const u32 aLo = smb + GX_LO + mi*16*272 + fofs;
    const u32 bHi = smb + GW_HI + half*128 + fofs;
    const u32 bLo = smb + GW_LO + half*128 + fofs;

    #pragma unroll 1
    for (int kk = 0; kk < 8; kk++) {
        u32 ah[4], al[4];
        ldsm4(ah, aHi + kk*32);
        ldsm4(al, aLo + kk*32);
        u32 bh[16], bl[16];
        #pragma unroll
        for (int nt = 0; nt < 4; nt++) {
            ldsm4t(bh + nt*4, bHi + kk*16*272 + nt*32);
            ldsm4t(bl + nt*4, bLo + kk*16*272 + nt*32);
        }
        #pragma unroll
        for (int n8 = 0; n8 < 8; n8++) {
            mma16816(c[n8], ah, bh + n8*2);
            mma16816(c[n8], ah, bl + n8*2);
            mma16816(c[n8], al, bh + n8*2);
        }
    }

    const int grow0 = rt*64 + mi*16 + r;
    #pragma unroll
    for (int n8 = 0; n8 < 8; n8++) {
        const int col = half*64 + n8*8 + 2*qq;
        const float2 bv = *(const float2*)(bo + col);
        #pragma unroll
        for (int rr = 0; rr < 2; rr++) {
            const int grow = grow0 + rr*8;
            float2 v = make_float2(c[n8][2*rr] + bv.x, c[n8][2*rr+1] + bv.y);
            *(float2*)(out + (size_t)grow*128 + col) = v;
        }
    }
}

// ---------------------------------------------------------------------------
extern "C" void kernel_launch(void* const* d_in, const int* in_sizes, int n_in,
                              void* d_out, int out_size)
{
    const float* x   = (const float*)d_in[0];
    const float* adj = (const float*)d_in[1];
    const float* Wq  = (const float*)d_in[2];
    const float* Wk  = (const float*)d_in[3];
    const float* Wv  = (const float*)d_in[4];
    const float* Wo  = (const float*)d_in[5];
    const float* bo  = (const float*)d_in[6];
    float* out = (float*)d_out;

    cudaFuncSetAttribute(qkv_mma,  cudaFuncAttributeMaxDynamicSharedMemorySize, GSMEM);
    cudaFuncSetAttribute(attn_mma, cudaFuncAttributeMaxDynamicSharedMemorySize, ASMEM);
    cudaFuncSetAttribute(out_mma,  cudaFuncAttributeMaxDynamicSharedMemorySize, GSMEM);

    qkv_mma<<<dim3(Bz*Cz/64, 3), 256, GSMEM>>>(x, Wq, Wk, Wv);
    attn_mma<<<dim3(Cz/QT, Bz), 512, ASMEM>>>(adj);
    out_mma<<<Bz*Cz/64, 256, GSMEM>>>(Wo, bo, out);
}